// round 4
// baseline (speedup 1.0000x reference)
#include <cuda_runtime.h>
#include <cuda_bf16.h>
#include <math.h>

// EdgeEmbeddingBlock: out_r[b,k,i,j] = radial[b,i] * na[b,k] * ylm_r[b,j]
//                     out_i[b,k,i,j] = radial[b,i] * na[b,k] * ylm_i[b,j]
// E=60000, K=10, NMAX=8, J=16. Output [combined_r | combined_i], 614 MB written.
//
// Register-resident expansion (R3 structure). R4 single change: default
// write-back stores instead of __stcs — use the 126MB L2 as an elastic
// write buffer so DRAM drains at its own pace and residual writebacks
// overlap with the next graph replay's startup.

#define KATTR 10
#define F4_PER_EDGE 320          // 1280 floats / 4

#define SEL4(g,a,b,c,d) ((g)==0?(a):((g)==1?(b):((g)==2?(c):(d))))

__global__ __launch_bounds__(256, 6)
void edge_embed_kernel(const int* __restrict__ edge_index,
                       const float* __restrict__ lens,
                       const float* __restrict__ vecs,
                       const float* __restrict__ attrs,
                       float* __restrict__ out,
                       int E)
{
    const int warp = threadIdx.x >> 5;
    const int lane = threadIdx.x & 31;
    const int e = blockIdx.x * 8 + warp;
    if (e >= E) return;

    // ---- per-edge scalars (broadcast loads) ----
    const float x  = lens[e];
    const float vx = vecs[3 * e + 0];
    const float vy = vecs[3 * e + 1];
    const float vz = vecs[3 * e + 2];
    const int sender = edge_index[e];   // edge_index[0, e]

    // lanes 0..9: node attrs for shuffle distribution
    float na_v = 0.0f;
    if (lane < KATTR) na_v = attrs[sender * KATTR + lane];

    // ---- radial: each lane computes rad[lane>>2] (poly cutoff p=6, R_CUT=5) ----
    const float u  = x * 0.2f;
    const float u2 = u * u, u3 = u2 * u;
    const float u6 = u3 * u3, u7 = u6 * u, u8 = u7 * u;
    float env = 1.0f - 28.0f * u6 + 48.0f * u7 - 21.0f * u8;
    env = (u < 1.0f) ? env : 0.0f;
    const float base = 0.63245553203f * env / x;          // sqrt(2/5) * env / x
    const float w = (float)((lane >> 2) + 1) * 0.62831853071f;  // n*pi/R_CUT
    const float r_l = base * sinf(w * x);

    // ---- zonal harmonics (all lanes, straight-line) ----
    const float nrm = sqrtf(vx * vx + vy * vy + vz * vz);
    const float inv = 1.0f / fmaxf(nrm, 1e-9f);
    const float ux = vx * inv, uy = vy * inv, uz = vz * inv;
    const float ct  = uz;
    const float st2 = fmaxf(1.0f - ct * ct, 0.0f);
    const float st  = sqrtf(st2);
    const float rxy = sqrtf(ux * ux + uy * uy);
    float c1, s1;
    if (rxy > 0.0f) { const float ir = 1.0f / rxy; c1 = ux * ir; s1 = uy * ir; }
    else            { c1 = 1.0f; s1 = 0.0f; }
    const float c2 = 2.0f * c1 * c1 - 1.0f;
    const float s2 = 2.0f * s1 * c1;
    const float c3 = c1 * c2 - s1 * s2;
    const float s3 = s1 * c2 + c1 * s2;

    const float P11 = -st;
    const float P22 = 3.0f * st2;
    const float P33 = -15.0f * st2 * st;
    const float P21 = -3.0f * ct * st;
    const float P32 = 15.0f * ct * st2;
    const float P20 = 1.5f * ct * ct - 0.5f;
    const float P31 = 0.5f * (5.0f * ct * P21 + 3.0f * st);
    const float P30 = ct * (2.5f * ct * ct - 1.5f);

    const float n00 = 0.28209479177f;
    const float n10 = 0.48860251190f, n11 = 0.34549414947f;
    const float n20 = 0.63078313051f, n21 = 0.25751613469f, n22 = 0.12875806734f;
    const float n30 = 0.74635266518f, n31 = 0.21545345607f, n32 = 0.06813236028f,
                n33 = 0.02781492157f;

    const float a  = n11 * P11;
    const float b1 = n21 * P21, b2 = n22 * P22;
    const float d1 = n31 * P31, d2 = n32 * P32, d3 = n33 * P33;

    // ylm groups (j = 4g .. 4g+3), select this lane's group g = lane & 3
    const int g = lane & 3;
    float4 yr4, yi4;
    yr4.x = SEL4(g, n00,       b2 * c2,   b2 * c2,  n30 * P30);
    yr4.y = SEL4(g, -a * c1,  -b1 * c1,  -d3 * c3,  d1 * c1);
    yr4.z = SEL4(g, n10 * ct,  n20 * P20, d2 * c2,  d2 * c2);
    yr4.w = SEL4(g, a * c1,    b1 * c1,  -d1 * c1,  d3 * c3);
    yi4.x = SEL4(g, 0.0f,     -b2 * s2,   b2 * s2,  0.0f);
    yi4.y = SEL4(g, a * s1,    b1 * s1,   d3 * s3,  d1 * s1);
    yi4.z = SEL4(g, 0.0f,      0.0f,     -d2 * s2,  d2 * s2);
    yi4.w = SEL4(g, a * s1,    b1 * s1,   d1 * s1,  d3 * s3);

    // ---- 320 float4 per half, coalesced stores (default write-back) ----
    float4* __restrict__ out4 = (float4*)out;
    const long long base_r = (long long)e * F4_PER_EDGE + lane;
    const long long base_i = ((long long)E + e) * F4_PER_EDGE + lane;

    #pragma unroll
    for (int it = 0; it < KATTR; ++it) {
        const float s = r_l * __shfl_sync(0xffffffffu, na_v, it);
        float4 orr = make_float4(s * yr4.x, s * yr4.y, s * yr4.z, s * yr4.w);
        float4 oii = make_float4(s * yi4.x, s * yi4.y, s * yi4.z, s * yi4.w);
        out4[base_r + 32 * it] = orr;
        out4[base_i + 32 * it] = oii;
    }
}

extern "C" void kernel_launch(void* const* d_in, const int* in_sizes, int n_in,
                              void* d_out, int out_size)
{
    const int*   edge_index = (const int*)d_in[0];    // (2, E) int32
    const float* lens       = (const float*)d_in[1];  // (E, 1) f32
    const float* vecs       = (const float*)d_in[2];  // (E, 3) f32
    const float* attrs      = (const float*)d_in[3];  // (N_NODES, 10) f32
    float* out = (float*)d_out;

    const int E = in_sizes[1];   // edge_lenghts element count
    const int blocks = (E + 7) / 8;
    edge_embed_kernel<<<blocks, 256>>>(edge_index, lens, vecs, attrs, out, E);
}

// round 5
// speedup vs baseline: 1.0011x; 1.0011x over previous
#include <cuda_runtime.h>
#include <cuda_bf16.h>
#include <math.h>

// EdgeEmbeddingBlock: out_r[b,k,i,j] = radial[b,i] * na[b,k] * ylm_r[b,j]
//                     out_i[b,k,i,j] = radial[b,i] * na[b,k] * ylm_i[b,j]
// E=60000, K=10, NMAX=8, J=16. Output [combined_r | combined_i], 614 MB written.
//
// R3 register-resident structure + __stcs streaming stores (best: 86.5us).
// R5 single change: __launch_bounds__(256, 8) -> cap regs to 32, raising
// residency 48 -> 64 warps/SM for more outstanding stores (DRAM busy 80% -> ?).

#define KATTR 10
#define F4_PER_EDGE 320          // 1280 floats / 4

#define SEL4(g,a,b,c,d) ((g)==0?(a):((g)==1?(b):((g)==2?(c):(d))))

__global__ __launch_bounds__(256, 8)
void edge_embed_kernel(const int* __restrict__ edge_index,
                       const float* __restrict__ lens,
                       const float* __restrict__ vecs,
                       const float* __restrict__ attrs,
                       float* __restrict__ out,
                       int E)
{
    const int warp = threadIdx.x >> 5;
    const int lane = threadIdx.x & 31;
    const int e = blockIdx.x * 8 + warp;
    if (e >= E) return;

    // ---- per-edge scalars (broadcast loads) ----
    const float x  = lens[e];
    const float vx = vecs[3 * e + 0];
    const float vy = vecs[3 * e + 1];
    const float vz = vecs[3 * e + 2];
    const int sender = edge_index[e];   // edge_index[0, e]

    // lanes 0..9: node attrs for shuffle distribution
    float na_v = 0.0f;
    if (lane < KATTR) na_v = attrs[sender * KATTR + lane];

    // ---- radial: each lane computes rad[lane>>2] (poly cutoff p=6, R_CUT=5) ----
    const float u  = x * 0.2f;
    const float u2 = u * u, u3 = u2 * u;
    const float u6 = u3 * u3, u7 = u6 * u, u8 = u7 * u;
    float env = 1.0f - 28.0f * u6 + 48.0f * u7 - 21.0f * u8;
    env = (u < 1.0f) ? env : 0.0f;
    const float base = 0.63245553203f * env / x;          // sqrt(2/5) * env / x
    const float w = (float)((lane >> 2) + 1) * 0.62831853071f;  // n*pi/R_CUT
    const float r_l = base * sinf(w * x);

    // ---- zonal harmonics (all lanes, straight-line) ----
    const float nrm = sqrtf(vx * vx + vy * vy + vz * vz);
    const float inv = 1.0f / fmaxf(nrm, 1e-9f);
    const float ux = vx * inv, uy = vy * inv, uz = vz * inv;
    const float ct  = uz;
    const float st2 = fmaxf(1.0f - ct * ct, 0.0f);
    const float st  = sqrtf(st2);
    const float rxy = sqrtf(ux * ux + uy * uy);
    float c1, s1;
    if (rxy > 0.0f) { const float ir = 1.0f / rxy; c1 = ux * ir; s1 = uy * ir; }
    else            { c1 = 1.0f; s1 = 0.0f; }
    const float c2 = 2.0f * c1 * c1 - 1.0f;
    const float s2 = 2.0f * s1 * c1;
    const float c3 = c1 * c2 - s1 * s2;
    const float s3 = s1 * c2 + c1 * s2;

    const float P11 = -st;
    const float P22 = 3.0f * st2;
    const float P33 = -15.0f * st2 * st;
    const float P21 = -3.0f * ct * st;
    const float P32 = 15.0f * ct * st2;
    const float P20 = 1.5f * ct * ct - 0.5f;
    const float P31 = 0.5f * (5.0f * ct * P21 + 3.0f * st);
    const float P30 = ct * (2.5f * ct * ct - 1.5f);

    const float n00 = 0.28209479177f;
    const float n10 = 0.48860251190f, n11 = 0.34549414947f;
    const float n20 = 0.63078313051f, n21 = 0.25751613469f, n22 = 0.12875806734f;
    const float n30 = 0.74635266518f, n31 = 0.21545345607f, n32 = 0.06813236028f,
                n33 = 0.02781492157f;

    const float a  = n11 * P11;
    const float b1 = n21 * P21, b2 = n22 * P22;
    const float d1 = n31 * P31, d2 = n32 * P32, d3 = n33 * P33;

    // ylm groups (j = 4g .. 4g+3), select this lane's group g = lane & 3
    const int g = lane & 3;
    float4 yr4, yi4;
    yr4.x = SEL4(g, n00,       b2 * c2,   b2 * c2,  n30 * P30);
    yr4.y = SEL4(g, -a * c1,  -b1 * c1,  -d3 * c3,  d1 * c1);
    yr4.z = SEL4(g, n10 * ct,  n20 * P20, d2 * c2,  d2 * c2);
    yr4.w = SEL4(g, a * c1,    b1 * c1,  -d1 * c1,  d3 * c3);
    yi4.x = SEL4(g, 0.0f,     -b2 * s2,   b2 * s2,  0.0f);
    yi4.y = SEL4(g, a * s1,    b1 * s1,   d3 * s3,  d1 * s1);
    yi4.z = SEL4(g, 0.0f,      0.0f,     -d2 * s2,  d2 * s2);
    yi4.w = SEL4(g, a * s1,    b1 * s1,   d1 * s1,  d3 * s3);

    // ---- 320 float4 per half, coalesced streaming stores ----
    float4* __restrict__ out4 = (float4*)out;
    const long long base_r = (long long)e * F4_PER_EDGE + lane;
    const long long base_i = ((long long)E + e) * F4_PER_EDGE + lane;

    #pragma unroll
    for (int it = 0; it < KATTR; ++it) {
        const float s = r_l * __shfl_sync(0xffffffffu, na_v, it);
        float4 orr = make_float4(s * yr4.x, s * yr4.y, s * yr4.z, s * yr4.w);
        float4 oii = make_float4(s * yi4.x, s * yi4.y, s * yi4.z, s * yi4.w);
        __stcs(&out4[base_r + 32 * it], orr);
        __stcs(&out4[base_i + 32 * it], oii);
    }
}

extern "C" void kernel_launch(void* const* d_in, const int* in_sizes, int n_in,
                              void* d_out, int out_size)
{
    const int*   edge_index = (const int*)d_in[0];    // (2, E) int32
    const float* lens       = (const float*)d_in[1];  // (E, 1) f32
    const float* vecs       = (const float*)d_in[2];  // (E, 3) f32
    const float* attrs      = (const float*)d_in[3];  // (N_NODES, 10) f32
    float* out = (float*)d_out;

    const int E = in_sizes[1];   // edge_lenghts element count
    const int blocks = (E + 7) / 8;
    edge_embed_kernel<<<blocks, 256>>>(edge_index, lens, vecs, attrs, out, E);
}

// round 6
// speedup vs baseline: 1.0054x; 1.0043x over previous
#include <cuda_runtime.h>
#include <cuda_bf16.h>
#include <math.h>

// EdgeEmbeddingBlock: out_r[b,k,i,j] = radial[b,i] * na[b,k] * ylm_r[b,j]
//                     out_i[b,k,i,j] = radial[b,i] * na[b,k] * ylm_i[b,j]
// E=60000, K=10, NMAX=8, J=16. Output [combined_r | combined_i], 614 MB written.
//
// R3 register-resident structure + __stcs streaming stores (best: 86.5us).
// R5 single change: __launch_bounds__(256, 8) -> cap regs to 32, raising
// residency 48 -> 64 warps/SM for more outstanding stores (DRAM busy 80% -> ?).

#define KATTR 10
#define F4_PER_EDGE 320          // 1280 floats / 4

#define SEL4(g,a,b,c,d) ((g)==0?(a):((g)==1?(b):((g)==2?(c):(d))))

__global__ __launch_bounds__(256, 8)
void edge_embed_kernel(const int* __restrict__ edge_index,
                       const float* __restrict__ lens,
                       const float* __restrict__ vecs,
                       const float* __restrict__ attrs,
                       float* __restrict__ out,
                       int E)
{
    const int warp = threadIdx.x >> 5;
    const int lane = threadIdx.x & 31;
    const int e = blockIdx.x * 8 + warp;
    if (e >= E) return;

    // ---- per-edge scalars (broadcast loads) ----
    const float x  = lens[e];
    const float vx = vecs[3 * e + 0];
    const float vy = vecs[3 * e + 1];
    const float vz = vecs[3 * e + 2];
    const int sender = edge_index[e];   // edge_index[0, e]

    // lanes 0..9: node attrs for shuffle distribution
    float na_v = 0.0f;
    if (lane < KATTR) na_v = attrs[sender * KATTR + lane];

    // ---- radial: each lane computes rad[lane>>2] (poly cutoff p=6, R_CUT=5) ----
    const float u  = x * 0.2f;
    const float u2 = u * u, u3 = u2 * u;
    const float u6 = u3 * u3, u7 = u6 * u, u8 = u7 * u;
    float env = 1.0f - 28.0f * u6 + 48.0f * u7 - 21.0f * u8;
    env = (u < 1.0f) ? env : 0.0f;
    const float base = 0.63245553203f * env / x;          // sqrt(2/5) * env / x
    const float w = (float)((lane >> 2) + 1) * 0.62831853071f;  // n*pi/R_CUT
    const float r_l = base * sinf(w * x);

    // ---- zonal harmonics (all lanes, straight-line) ----
    const float nrm = sqrtf(vx * vx + vy * vy + vz * vz);
    const float inv = 1.0f / fmaxf(nrm, 1e-9f);
    const float ux = vx * inv, uy = vy * inv, uz = vz * inv;
    const float ct  = uz;
    const float st2 = fmaxf(1.0f - ct * ct, 0.0f);
    const float st  = sqrtf(st2);
    const float rxy = sqrtf(ux * ux + uy * uy);
    float c1, s1;
    if (rxy > 0.0f) { const float ir = 1.0f / rxy; c1 = ux * ir; s1 = uy * ir; }
    else            { c1 = 1.0f; s1 = 0.0f; }
    const float c2 = 2.0f * c1 * c1 - 1.0f;
    const float s2 = 2.0f * s1 * c1;
    const float c3 = c1 * c2 - s1 * s2;
    const float s3 = s1 * c2 + c1 * s2;

    const float P11 = -st;
    const float P22 = 3.0f * st2;
    const float P33 = -15.0f * st2 * st;
    const float P21 = -3.0f * ct * st;
    const float P32 = 15.0f * ct * st2;
    const float P20 = 1.5f * ct * ct - 0.5f;
    const float P31 = 0.5f * (5.0f * ct * P21 + 3.0f * st);
    const float P30 = ct * (2.5f * ct * ct - 1.5f);

    const float n00 = 0.28209479177f;
    const float n10 = 0.48860251190f, n11 = 0.34549414947f;
    const float n20 = 0.63078313051f, n21 = 0.25751613469f, n22 = 0.12875806734f;
    const float n30 = 0.74635266518f, n31 = 0.21545345607f, n32 = 0.06813236028f,
                n33 = 0.02781492157f;

    const float a  = n11 * P11;
    const float b1 = n21 * P21, b2 = n22 * P22;
    const float d1 = n31 * P31, d2 = n32 * P32, d3 = n33 * P33;

    // ylm groups (j = 4g .. 4g+3), select this lane's group g = lane & 3
    const int g = lane & 3;
    float4 yr4, yi4;
    yr4.x = SEL4(g, n00,       b2 * c2,   b2 * c2,  n30 * P30);
    yr4.y = SEL4(g, -a * c1,  -b1 * c1,  -d3 * c3,  d1 * c1);
    yr4.z = SEL4(g, n10 * ct,  n20 * P20, d2 * c2,  d2 * c2);
    yr4.w = SEL4(g, a * c1,    b1 * c1,  -d1 * c1,  d3 * c3);
    yi4.x = SEL4(g, 0.0f,     -b2 * s2,   b2 * s2,  0.0f);
    yi4.y = SEL4(g, a * s1,    b1 * s1,   d3 * s3,  d1 * s1);
    yi4.z = SEL4(g, 0.0f,      0.0f,     -d2 * s2,  d2 * s2);
    yi4.w = SEL4(g, a * s1,    b1 * s1,   d1 * s1,  d3 * s3);

    // ---- 320 float4 per half, coalesced streaming stores ----
    float4* __restrict__ out4 = (float4*)out;
    const long long base_r = (long long)e * F4_PER_EDGE + lane;
    const long long base_i = ((long long)E + e) * F4_PER_EDGE + lane;

    #pragma unroll
    for (int it = 0; it < KATTR; ++it) {
        const float s = r_l * __shfl_sync(0xffffffffu, na_v, it);
        float4 orr = make_float4(s * yr4.x, s * yr4.y, s * yr4.z, s * yr4.w);
        float4 oii = make_float4(s * yi4.x, s * yi4.y, s * yi4.z, s * yi4.w);
        __stcs(&out4[base_r + 32 * it], orr);
        __stcs(&out4[base_i + 32 * it], oii);
    }
}

extern "C" void kernel_launch(void* const* d_in, const int* in_sizes, int n_in,
                              void* d_out, int out_size)
{
    const int*   edge_index = (const int*)d_in[0];    // (2, E) int32
    const float* lens       = (const float*)d_in[1];  // (E, 1) f32
    const float* vecs       = (const float*)d_in[2];  // (E, 3) f32
    const float* attrs      = (const float*)d_in[3];  // (N_NODES, 10) f32
    float* out = (float*)d_out;

    const int E = in_sizes[1];   // edge_lenghts element count
    const int blocks = (E + 7) / 8;
    edge_embed_kernel<<<blocks, 256>>>(edge_index, lens, vecs, attrs, out, E);
}

// round 7
// speedup vs baseline: 1.0104x; 1.0050x over previous
#include <cuda_runtime.h>
#include <cuda_bf16.h>
#include <math.h>

// EdgeEmbeddingBlock: out_r[b,k,i,j] = radial[b,i] * na[b,k] * ylm_r[b,j]
//                     out_i[b,k,i,j] = radial[b,i] * na[b,k] * ylm_i[b,j]
// E=60000, K=10, NMAX=8, J=16. Output [combined_r | combined_i], 614 MB written.
//
// R3 register-resident structure (best: 86.5us @ __stcs, 39 regs, occ 6).
// R7 single change: __stwt write-through stores — no dirty L2 lines, zero
// residual drain at the replay boundary.

#define KATTR 10
#define F4_PER_EDGE 320          // 1280 floats / 4

#define SEL4(g,a,b,c,d) ((g)==0?(a):((g)==1?(b):((g)==2?(c):(d))))

__global__ __launch_bounds__(256, 6)
void edge_embed_kernel(const int* __restrict__ edge_index,
                       const float* __restrict__ lens,
                       const float* __restrict__ vecs,
                       const float* __restrict__ attrs,
                       float* __restrict__ out,
                       int E)
{
    const int warp = threadIdx.x >> 5;
    const int lane = threadIdx.x & 31;
    const int e = blockIdx.x * 8 + warp;
    if (e >= E) return;

    // ---- per-edge scalars (broadcast loads) ----
    const float x  = lens[e];
    const float vx = vecs[3 * e + 0];
    const float vy = vecs[3 * e + 1];
    const float vz = vecs[3 * e + 2];
    const int sender = edge_index[e];   // edge_index[0, e]

    // lanes 0..9: node attrs for shuffle distribution
    float na_v = 0.0f;
    if (lane < KATTR) na_v = attrs[sender * KATTR + lane];

    // ---- radial: each lane computes rad[lane>>2] (poly cutoff p=6, R_CUT=5) ----
    const float u  = x * 0.2f;
    const float u2 = u * u, u3 = u2 * u;
    const float u6 = u3 * u3, u7 = u6 * u, u8 = u7 * u;
    float env = 1.0f - 28.0f * u6 + 48.0f * u7 - 21.0f * u8;
    env = (u < 1.0f) ? env : 0.0f;
    const float base = 0.63245553203f * env / x;          // sqrt(2/5) * env / x
    const float w = (float)((lane >> 2) + 1) * 0.62831853071f;  // n*pi/R_CUT
    const float r_l = base * sinf(w * x);

    // ---- zonal harmonics (all lanes, straight-line) ----
    const float nrm = sqrtf(vx * vx + vy * vy + vz * vz);
    const float inv = 1.0f / fmaxf(nrm, 1e-9f);
    const float ux = vx * inv, uy = vy * inv, uz = vz * inv;
    const float ct  = uz;
    const float st2 = fmaxf(1.0f - ct * ct, 0.0f);
    const float st  = sqrtf(st2);
    const float rxy = sqrtf(ux * ux + uy * uy);
    float c1, s1;
    if (rxy > 0.0f) { const float ir = 1.0f / rxy; c1 = ux * ir; s1 = uy * ir; }
    else            { c1 = 1.0f; s1 = 0.0f; }
    const float c2 = 2.0f * c1 * c1 - 1.0f;
    const float s2 = 2.0f * s1 * c1;
    const float c3 = c1 * c2 - s1 * s2;
    const float s3 = s1 * c2 + c1 * s2;

    const float P11 = -st;
    const float P22 = 3.0f * st2;
    const float P33 = -15.0f * st2 * st;
    const float P21 = -3.0f * ct * st;
    const float P32 = 15.0f * ct * st2;
    const float P20 = 1.5f * ct * ct - 0.5f;
    const float P31 = 0.5f * (5.0f * ct * P21 + 3.0f * st);
    const float P30 = ct * (2.5f * ct * ct - 1.5f);

    const float n00 = 0.28209479177f;
    const float n10 = 0.48860251190f, n11 = 0.34549414947f;
    const float n20 = 0.63078313051f, n21 = 0.25751613469f, n22 = 0.12875806734f;
    const float n30 = 0.74635266518f, n31 = 0.21545345607f, n32 = 0.06813236028f,
                n33 = 0.02781492157f;

    const float a  = n11 * P11;
    const float b1 = n21 * P21, b2 = n22 * P22;
    const float d1 = n31 * P31, d2 = n32 * P32, d3 = n33 * P33;

    // ylm groups (j = 4g .. 4g+3), select this lane's group g = lane & 3
    const int g = lane & 3;
    float4 yr4, yi4;
    yr4.x = SEL4(g, n00,       b2 * c2,   b2 * c2,  n30 * P30);
    yr4.y = SEL4(g, -a * c1,  -b1 * c1,  -d3 * c3,  d1 * c1);
    yr4.z = SEL4(g, n10 * ct,  n20 * P20, d2 * c2,  d2 * c2);
    yr4.w = SEL4(g, a * c1,    b1 * c1,  -d1 * c1,  d3 * c3);
    yi4.x = SEL4(g, 0.0f,     -b2 * s2,   b2 * s2,  0.0f);
    yi4.y = SEL4(g, a * s1,    b1 * s1,   d3 * s3,  d1 * s1);
    yi4.z = SEL4(g, 0.0f,      0.0f,     -d2 * s2,  d2 * s2);
    yi4.w = SEL4(g, a * s1,    b1 * s1,   d1 * s1,  d3 * s3);

    // ---- 320 float4 per half, coalesced write-through stores ----
    float4* __restrict__ out4 = (float4*)out;
    const long long base_r = (long long)e * F4_PER_EDGE + lane;
    const long long base_i = ((long long)E + e) * F4_PER_EDGE + lane;

    #pragma unroll
    for (int it = 0; it < KATTR; ++it) {
        const float s = r_l * __shfl_sync(0xffffffffu, na_v, it);
        float4 orr = make_float4(s * yr4.x, s * yr4.y, s * yr4.z, s * yr4.w);
        float4 oii = make_float4(s * yi4.x, s * yi4.y, s * yi4.z, s * yi4.w);
        __stwt(&out4[base_r + 32 * it], orr);
        __stwt(&out4[base_i + 32 * it], oii);
    }
}

extern "C" void kernel_launch(void* const* d_in, const int* in_sizes, int n_in,
                              void* d_out, int out_size)
{
    const int*   edge_index = (const int*)d_in[0];    // (2, E) int32
    const float* lens       = (const float*)d_in[1];  // (E, 1) f32
    const float* vecs       = (const float*)d_in[2];  // (E, 3) f32
    const float* attrs      = (const float*)d_in[3];  // (N_NODES, 10) f32
    float* out = (float*)d_out;

    const int E = in_sizes[1];   // edge_lenghts element count
    const int blocks = (E + 7) / 8;
    edge_embed_kernel<<<blocks, 256>>>(edge_index, lens, vecs, attrs, out, E);
}

// round 8
// speedup vs baseline: 1.0247x; 1.0142x over previous
#include <cuda_runtime.h>
#include <cuda_bf16.h>
#include <math.h>

// EdgeEmbeddingBlock: out_r[b,k,i,j] = radial[b,i] * na[b,k] * ylm_r[b,j]
//                     out_i[b,k,i,j] = radial[b,i] * na[b,k] * ylm_i[b,j]
// E=60000, K=10, NMAX=8, J=16. Output [combined_r | combined_i], 614 MB written.
//
// Converged structure: register-resident expansion, 1 warp/edge, 20 STG.128
// per lane with __stcs (best drain behavior of {stcs, stwt, write-back}).
// R8: block 256 -> 512 to halve CTA churn; residency unchanged (48 warps/SM).

#define KATTR 10
#define F4_PER_EDGE 320          // 1280 floats / 4
#define WARPS_CTA 16

#define SEL4(g,a,b,c,d) ((g)==0?(a):((g)==1?(b):((g)==2?(c):(d))))

__global__ __launch_bounds__(WARPS_CTA * 32, 3)
void edge_embed_kernel(const int* __restrict__ edge_index,
                       const float* __restrict__ lens,
                       const float* __restrict__ vecs,
                       const float* __restrict__ attrs,
                       float* __restrict__ out,
                       int E)
{
    const int warp = threadIdx.x >> 5;
    const int lane = threadIdx.x & 31;
    const int e = blockIdx.x * WARPS_CTA + warp;
    if (e >= E) return;

    // ---- per-edge scalars (broadcast loads) ----
    const float x  = lens[e];
    const float vx = vecs[3 * e + 0];
    const float vy = vecs[3 * e + 1];
    const float vz = vecs[3 * e + 2];
    const int sender = edge_index[e];   // edge_index[0, e]

    // lanes 0..9: node attrs for shuffle distribution
    float na_v = 0.0f;
    if (lane < KATTR) na_v = attrs[sender * KATTR + lane];

    // ---- radial: each lane computes rad[lane>>2] (poly cutoff p=6, R_CUT=5) ----
    const float u  = x * 0.2f;
    const float u2 = u * u, u3 = u2 * u;
    const float u6 = u3 * u3, u7 = u6 * u, u8 = u7 * u;
    float env = 1.0f - 28.0f * u6 + 48.0f * u7 - 21.0f * u8;
    env = (u < 1.0f) ? env : 0.0f;
    const float base = 0.63245553203f * env / x;          // sqrt(2/5) * env / x
    const float w = (float)((lane >> 2) + 1) * 0.62831853071f;  // n*pi/R_CUT
    const float r_l = base * sinf(w * x);

    // ---- zonal harmonics (all lanes, straight-line) ----
    const float nrm = sqrtf(vx * vx + vy * vy + vz * vz);
    const float inv = 1.0f / fmaxf(nrm, 1e-9f);
    const float ux = vx * inv, uy = vy * inv, uz = vz * inv;
    const float ct  = uz;
    const float st2 = fmaxf(1.0f - ct * ct, 0.0f);
    const float st  = sqrtf(st2);
    const float rxy = sqrtf(ux * ux + uy * uy);
    float c1, s1;
    if (rxy > 0.0f) { const float ir = 1.0f / rxy; c1 = ux * ir; s1 = uy * ir; }
    else            { c1 = 1.0f; s1 = 0.0f; }
    const float c2 = 2.0f * c1 * c1 - 1.0f;
    const float s2 = 2.0f * s1 * c1;
    const float c3 = c1 * c2 - s1 * s2;
    const float s3 = s1 * c2 + c1 * s2;

    const float P11 = -st;
    const float P22 = 3.0f * st2;
    const float P33 = -15.0f * st2 * st;
    const float P21 = -3.0f * ct * st;
    const float P32 = 15.0f * ct * st2;
    const float P20 = 1.5f * ct * ct - 0.5f;
    const float P31 = 0.5f * (5.0f * ct * P21 + 3.0f * st);
    const float P30 = ct * (2.5f * ct * ct - 1.5f);

    const float n00 = 0.28209479177f;
    const float n10 = 0.48860251190f, n11 = 0.34549414947f;
    const float n20 = 0.63078313051f, n21 = 0.25751613469f, n22 = 0.12875806734f;
    const float n30 = 0.74635266518f, n31 = 0.21545345607f, n32 = 0.06813236028f,
                n33 = 0.02781492157f;

    const float a  = n11 * P11;
    const float b1 = n21 * P21, b2 = n22 * P22;
    const float d1 = n31 * P31, d2 = n32 * P32, d3 = n33 * P33;

    // ylm groups (j = 4g .. 4g+3), select this lane's group g = lane & 3
    const int g = lane & 3;
    float4 yr4, yi4;
    yr4.x = SEL4(g, n00,       b2 * c2,   b2 * c2,  n30 * P30);
    yr4.y = SEL4(g, -a * c1,  -b1 * c1,  -d3 * c3,  d1 * c1);
    yr4.z = SEL4(g, n10 * ct,  n20 * P20, d2 * c2,  d2 * c2);
    yr4.w = SEL4(g, a * c1,    b1 * c1,  -d1 * c1,  d3 * c3);
    yi4.x = SEL4(g, 0.0f,     -b2 * s2,   b2 * s2,  0.0f);
    yi4.y = SEL4(g, a * s1,    b1 * s1,   d3 * s3,  d1 * s1);
    yi4.z = SEL4(g, 0.0f,      0.0f,     -d2 * s2,  d2 * s2);
    yi4.w = SEL4(g, a * s1,    b1 * s1,   d1 * s1,  d3 * s3);

    // ---- 320 float4 per half, coalesced streaming stores ----
    float4* __restrict__ out4 = (float4*)out;
    const long long base_r = (long long)e * F4_PER_EDGE + lane;
    const long long base_i = ((long long)E + e) * F4_PER_EDGE + lane;

    #pragma unroll
    for (int it = 0; it < KATTR; ++it) {
        const float s = r_l * __shfl_sync(0xffffffffu, na_v, it);
        float4 orr = make_float4(s * yr4.x, s * yr4.y, s * yr4.z, s * yr4.w);
        float4 oii = make_float4(s * yi4.x, s * yi4.y, s * yi4.z, s * yi4.w);
        __stcs(&out4[base_r + 32 * it], orr);
        __stcs(&out4[base_i + 32 * it], oii);
    }
}

extern "C" void kernel_launch(void* const* d_in, const int* in_sizes, int n_in,
                              void* d_out, int out_size)
{
    const int*   edge_index = (const int*)d_in[0];    // (2, E) int32
    const float* lens       = (const float*)d_in[1];  // (E, 1) f32
    const float* vecs       = (const float*)d_in[2];  // (E, 3) f32
    const float* attrs      = (const float*)d_in[3];  // (N_NODES, 10) f32
    float* out = (float*)d_out;

    const int E = in_sizes[1];   // edge_lenghts element count
    const int blocks = (E + WARPS_CTA - 1) / WARPS_CTA;
    edge_embed_kernel<<<blocks, WARPS_CTA * 32>>>(edge_index, lens, vecs, attrs, out, E);
}

// round 9
// speedup vs baseline: 1.0418x; 1.0166x over previous
#include <cuda_runtime.h>
#include <cuda_bf16.h>
#include <math.h>

// EdgeEmbeddingBlock: out_r[b,k,i,j] = radial[b,i] * na[b,k] * ylm_r[b,j]
//                     out_i[b,k,i,j] = radial[b,i] * na[b,k] * ylm_i[b,j]
// E=60000, K=10, NMAX=8, J=16. Output [combined_r | combined_i], 614 MB written.
//
// Best config (R3): register-resident expansion, 1 warp/edge, __stcs,
// 256 threads, occ 6, 39 regs. R9 single change: split r/i store loops so
// each warp issues 10 consecutive stores per region (DRAM row locality)
// instead of alternating between regions 307MB apart.

#define KATTR 10
#define F4_PER_EDGE 320          // 1280 floats / 4

#define SEL4(g,a,b,c,d) ((g)==0?(a):((g)==1?(b):((g)==2?(c):(d))))

__global__ __launch_bounds__(256, 6)
void edge_embed_kernel(const int* __restrict__ edge_index,
                       const float* __restrict__ lens,
                       const float* __restrict__ vecs,
                       const float* __restrict__ attrs,
                       float* __restrict__ out,
                       int E)
{
    const int warp = threadIdx.x >> 5;
    const int lane = threadIdx.x & 31;
    const int e = blockIdx.x * 8 + warp;
    if (e >= E) return;

    // ---- per-edge scalars (broadcast loads) ----
    const float x  = lens[e];
    const float vx = vecs[3 * e + 0];
    const float vy = vecs[3 * e + 1];
    const float vz = vecs[3 * e + 2];
    const int sender = edge_index[e];   // edge_index[0, e]

    // lanes 0..9: node attrs for shuffle distribution
    float na_v = 0.0f;
    if (lane < KATTR) na_v = attrs[sender * KATTR + lane];

    // ---- radial: each lane computes rad[lane>>2] (poly cutoff p=6, R_CUT=5) ----
    const float u  = x * 0.2f;
    const float u2 = u * u, u3 = u2 * u;
    const float u6 = u3 * u3, u7 = u6 * u, u8 = u7 * u;
    float env = 1.0f - 28.0f * u6 + 48.0f * u7 - 21.0f * u8;
    env = (u < 1.0f) ? env : 0.0f;
    const float base = 0.63245553203f * env / x;          // sqrt(2/5) * env / x
    const float w = (float)((lane >> 2) + 1) * 0.62831853071f;  // n*pi/R_CUT
    const float r_l = base * sinf(w * x);

    // ---- zonal harmonics (all lanes, straight-line) ----
    const float nrm = sqrtf(vx * vx + vy * vy + vz * vz);
    const float inv = 1.0f / fmaxf(nrm, 1e-9f);
    const float ux = vx * inv, uy = vy * inv, uz = vz * inv;
    const float ct  = uz;
    const float st2 = fmaxf(1.0f - ct * ct, 0.0f);
    const float st  = sqrtf(st2);
    const float rxy = sqrtf(ux * ux + uy * uy);
    float c1, s1;
    if (rxy > 0.0f) { const float ir = 1.0f / rxy; c1 = ux * ir; s1 = uy * ir; }
    else            { c1 = 1.0f; s1 = 0.0f; }
    const float c2 = 2.0f * c1 * c1 - 1.0f;
    const float s2 = 2.0f * s1 * c1;
    const float c3 = c1 * c2 - s1 * s2;
    const float s3 = s1 * c2 + c1 * s2;

    const float P11 = -st;
    const float P22 = 3.0f * st2;
    const float P33 = -15.0f * st2 * st;
    const float P21 = -3.0f * ct * st;
    const float P32 = 15.0f * ct * st2;
    const float P20 = 1.5f * ct * ct - 0.5f;
    const float P31 = 0.5f * (5.0f * ct * P21 + 3.0f * st);
    const float P30 = ct * (2.5f * ct * ct - 1.5f);

    const float n00 = 0.28209479177f;
    const float n10 = 0.48860251190f, n11 = 0.34549414947f;
    const float n20 = 0.63078313051f, n21 = 0.25751613469f, n22 = 0.12875806734f;
    const float n30 = 0.74635266518f, n31 = 0.21545345607f, n32 = 0.06813236028f,
                n33 = 0.02781492157f;

    const float a  = n11 * P11;
    const float b1 = n21 * P21, b2 = n22 * P22;
    const float d1 = n31 * P31, d2 = n32 * P32, d3 = n33 * P33;

    // ylm groups (j = 4g .. 4g+3), select this lane's group g = lane & 3
    const int g = lane & 3;
    float4 yr4, yi4;
    yr4.x = SEL4(g, n00,       b2 * c2,   b2 * c2,  n30 * P30);
    yr4.y = SEL4(g, -a * c1,  -b1 * c1,  -d3 * c3,  d1 * c1);
    yr4.z = SEL4(g, n10 * ct,  n20 * P20, d2 * c2,  d2 * c2);
    yr4.w = SEL4(g, a * c1,    b1 * c1,  -d1 * c1,  d3 * c3);
    yi4.x = SEL4(g, 0.0f,     -b2 * s2,   b2 * s2,  0.0f);
    yi4.y = SEL4(g, a * s1,    b1 * s1,   d3 * s3,  d1 * s1);
    yi4.z = SEL4(g, 0.0f,      0.0f,     -d2 * s2,  d2 * s2);
    yi4.w = SEL4(g, a * s1,    b1 * s1,   d1 * s1,  d3 * s3);

    // ---- per-k scales (shuffled once, reused by both passes) ----
    float sk[KATTR];
    #pragma unroll
    for (int it = 0; it < KATTR; ++it)
        sk[it] = r_l * __shfl_sync(0xffffffffu, na_v, it);

    // ---- pass 1: 10 consecutive STG.128 into the r half ----
    float4* __restrict__ out4 = (float4*)out;
    const long long base_r = (long long)e * F4_PER_EDGE + lane;
    #pragma unroll
    for (int it = 0; it < KATTR; ++it) {
        const float s = sk[it];
        float4 orr = make_float4(s * yr4.x, s * yr4.y, s * yr4.z, s * yr4.w);
        __stcs(&out4[base_r + 32 * it], orr);
    }

    // ---- pass 2: 10 consecutive STG.128 into the i half ----
    const long long base_i = ((long long)E + e) * F4_PER_EDGE + lane;
    #pragma unroll
    for (int it = 0; it < KATTR; ++it) {
        const float s = sk[it];
        float4 oii = make_float4(s * yi4.x, s * yi4.y, s * yi4.z, s * yi4.w);
        __stcs(&out4[base_i + 32 * it], oii);
    }
}

extern "C" void kernel_launch(void* const* d_in, const int* in_sizes, int n_in,
                              void* d_out, int out_size)
{
    const int*   edge_index = (const int*)d_in[0];    // (2, E) int32
    const float* lens       = (const float*)d_in[1];  // (E, 1) f32
    const float* vecs       = (const float*)d_in[2];  // (E, 3) f32
    const float* attrs      = (const float*)d_in[3];  // (N_NODES, 10) f32
    float* out = (float*)d_out;

    const int E = in_sizes[1];   // edge_lenghts element count
    const int blocks = (E + 7) / 8;
    edge_embed_kernel<<<blocks, 256>>>(edge_index, lens, vecs, attrs, out, E);
}

// round 10
// speedup vs baseline: 1.0449x; 1.0030x over previous
#include <cuda_runtime.h>
#include <cuda_bf16.h>
#include <math.h>

// EdgeEmbeddingBlock: out_r[b,k,i,j] = radial[b,i] * na[b,k] * ylm_r[b,j]
//                     out_i[b,k,i,j] = radial[b,i] * na[b,k] * ylm_i[b,j]
// E=60000, K=10, NMAX=8, J=16. Output [combined_r | combined_i], 614 MB written.
//
// CONVERGED config (86.5us, HBM write-path floor ~6.35 TB/s wire rate):
// register-resident expansion, 1 warp/edge, __stcs STG.128, 256-thread blocks.
// R10 trim: 32-bit output indexing (38.4M float4 < 2^31) — folds address math
// into immediate-offset stores off a single 32-bit base.

#define KATTR 10
#define F4_PER_EDGE 320u         // 1280 floats / 4

#define SEL4(g,a,b,c,d) ((g)==0?(a):((g)==1?(b):((g)==2?(c):(d))))

__global__ __launch_bounds__(256, 6)
void edge_embed_kernel(const int* __restrict__ edge_index,
                       const float* __restrict__ lens,
                       const float* __restrict__ vecs,
                       const float* __restrict__ attrs,
                       float* __restrict__ out,
                       int E)
{
    const int warp = threadIdx.x >> 5;
    const int lane = threadIdx.x & 31;
    const int e = blockIdx.x * 8 + warp;
    if (e >= E) return;

    // ---- per-edge scalars (broadcast loads) ----
    const float x  = lens[e];
    const float vx = vecs[3 * e + 0];
    const float vy = vecs[3 * e + 1];
    const float vz = vecs[3 * e + 2];
    const int sender = edge_index[e];   // edge_index[0, e]

    // lanes 0..9: node attrs for shuffle distribution
    float na_v = 0.0f;
    if (lane < KATTR) na_v = attrs[sender * KATTR + lane];

    // ---- radial: each lane computes rad[lane>>2] (poly cutoff p=6, R_CUT=5) ----
    const float u  = x * 0.2f;
    const float u2 = u * u, u3 = u2 * u;
    const float u6 = u3 * u3, u7 = u6 * u, u8 = u7 * u;
    float env = 1.0f - 28.0f * u6 + 48.0f * u7 - 21.0f * u8;
    env = (u < 1.0f) ? env : 0.0f;
    const float base = 0.63245553203f * env / x;          // sqrt(2/5) * env / x
    const float w = (float)((lane >> 2) + 1) * 0.62831853071f;  // n*pi/R_CUT
    const float r_l = base * sinf(w * x);

    // ---- zonal harmonics (all lanes, straight-line) ----
    const float nrm = sqrtf(vx * vx + vy * vy + vz * vz);
    const float inv = 1.0f / fmaxf(nrm, 1e-9f);
    const float ux = vx * inv, uy = vy * inv, uz = vz * inv;
    const float ct  = uz;
    const float st2 = fmaxf(1.0f - ct * ct, 0.0f);
    const float st  = sqrtf(st2);
    const float rxy = sqrtf(ux * ux + uy * uy);
    float c1, s1;
    if (rxy > 0.0f) { const float ir = 1.0f / rxy; c1 = ux * ir; s1 = uy * ir; }
    else            { c1 = 1.0f; s1 = 0.0f; }
    const float c2 = 2.0f * c1 * c1 - 1.0f;
    const float s2 = 2.0f * s1 * c1;
    const float c3 = c1 * c2 - s1 * s2;
    const float s3 = s1 * c2 + c1 * s2;

    const float P11 = -st;
    const float P22 = 3.0f * st2;
    const float P33 = -15.0f * st2 * st;
    const float P21 = -3.0f * ct * st;
    const float P32 = 15.0f * ct * st2;
    const float P20 = 1.5f * ct * ct - 0.5f;
    const float P31 = 0.5f * (5.0f * ct * P21 + 3.0f * st);
    const float P30 = ct * (2.5f * ct * ct - 1.5f);

    const float n00 = 0.28209479177f;
    const float n10 = 0.48860251190f, n11 = 0.34549414947f;
    const float n20 = 0.63078313051f, n21 = 0.25751613469f, n22 = 0.12875806734f;
    const float n30 = 0.74635266518f, n31 = 0.21545345607f, n32 = 0.06813236028f,
                n33 = 0.02781492157f;

    const float a  = n11 * P11;
    const float b1 = n21 * P21, b2 = n22 * P22;
    const float d1 = n31 * P31, d2 = n32 * P32, d3 = n33 * P33;

    // ylm groups (j = 4g .. 4g+3), select this lane's group g = lane & 3
    const int g = lane & 3;
    float4 yr4, yi4;
    yr4.x = SEL4(g, n00,       b2 * c2,   b2 * c2,  n30 * P30);
    yr4.y = SEL4(g, -a * c1,  -b1 * c1,  -d3 * c3,  d1 * c1);
    yr4.z = SEL4(g, n10 * ct,  n20 * P20, d2 * c2,  d2 * c2);
    yr4.w = SEL4(g, a * c1,    b1 * c1,  -d1 * c1,  d3 * c3);
    yi4.x = SEL4(g, 0.0f,     -b2 * s2,   b2 * s2,  0.0f);
    yi4.y = SEL4(g, a * s1,    b1 * s1,   d3 * s3,  d1 * s1);
    yi4.z = SEL4(g, 0.0f,      0.0f,     -d2 * s2,  d2 * s2);
    yi4.w = SEL4(g, a * s1,    b1 * s1,   d1 * s1,  d3 * s3);

    // ---- per-k scales (shuffled once, reused by both passes) ----
    float sk[KATTR];
    #pragma unroll
    for (int it = 0; it < KATTR; ++it)
        sk[it] = r_l * __shfl_sync(0xffffffffu, na_v, it);

    // ---- 32-bit indexed, immediate-offset streaming stores ----
    float4* __restrict__ out4 = (float4*)out;
    float4* __restrict__ pr = out4 + ((unsigned)e * F4_PER_EDGE + (unsigned)lane);
    float4* __restrict__ pi = out4 + (((unsigned)E + (unsigned)e) * F4_PER_EDGE + (unsigned)lane);

    #pragma unroll
    for (int it = 0; it < KATTR; ++it) {
        const float s = sk[it];
        float4 orr = make_float4(s * yr4.x, s * yr4.y, s * yr4.z, s * yr4.w);
        __stcs(pr + 32 * it, orr);
    }
    #pragma unroll
    for (int it = 0; it < KATTR; ++it) {
        const float s = sk[it];
        float4 oii = make_float4(s * yi4.x, s * yi4.y, s * yi4.z, s * yi4.w);
        __stcs(pi + 32 * it, oii);
    }
}

extern "C" void kernel_launch(void* const* d_in, const int* in_sizes, int n_in,
                              void* d_out, int out_size)
{
    const int*   edge_index = (const int*)d_in[0];    // (2, E) int32
    const float* lens       = (const float*)d_in[1];  // (E, 1) f32
    const float* vecs       = (const float*)d_in[2];  // (E, 3) f32
    const float* attrs      = (const float*)d_in[3];  // (N_NODES, 10) f32
    float* out = (float*)d_out;

    const int E = in_sizes[1];   // edge_lenghts element count
    const int blocks = (E + 7) / 8;
    edge_embed_kernel<<<blocks, 256>>>(edge_index, lens, vecs, attrs, out, E);
}